// round 6
// baseline (speedup 1.0000x reference)
#include <cuda_runtime.h>
#include <cuda_bf16.h>
#include <math.h>

// Shapes (fixed dataset):
//   x_all: [100000, 256] f32, n_id: [50000] i32, edge_index: [2, 300000] i32
//   W_sage: [256,256] f32, b_sage: [256] f32, W_cls: [3,256] f32, b_cls: [3] f32
//   out: [50000, 3] f32 (log_softmax)
//
// Algebra: out = log_softmax( mean_{j in N(i)+self}( x[j] ) @ Wc + bc )
//        = log_softmax( mean_{j}( x[j] @ Wc ) + bc )            (linearity)
// Project each node row to 3 floats ONCE, then aggregate 3-vectors over edges.
#define NMAX 50000
#define FDIM 256
#define F4   64      // FDIM / 4
#define CCLS 3

// Scratch (__device__ globals: allocation-free rule)
__device__ float  g_Wc [CCLS * FDIM];   // fused weight
__device__ float  g_bc [CCLS];          // fused bias
__device__ float4 g_z  [NMAX];          // per-node projected scores {s0,s1,s2, 1.0}
__device__ float4 g_acc[NMAX];          // accumulated {sum0,sum1,sum2, cnt}

// ---------------------------------------------------------------------------
// Kernel 0: parallel weight fusion. One warp per output element.
// ---------------------------------------------------------------------------
__global__ void k_init(const float* __restrict__ W_sage,
                       const float* __restrict__ b_sage,
                       const float* __restrict__ W_cls,
                       const float* __restrict__ b_cls) {
    int gid  = blockIdx.x * blockDim.x + threadIdx.x;
    int ww   = gid >> 5;
    int lane = gid & 31;
    const unsigned full = 0xffffffffu;

    if (ww < CCLS * FDIM) {
        int c = ww >> 8;          // ww / FDIM
        int k = ww & 255;         // ww % FDIM
        const float4* wrow = reinterpret_cast<const float4*>(W_sage + k * FDIM);
        const float4* crow = reinterpret_cast<const float4*>(W_cls  + c * FDIM);
        float4 a0 = __ldg(&wrow[lane]);      float4 b0 = __ldg(&crow[lane]);
        float4 a1 = __ldg(&wrow[lane + 32]); float4 b1 = __ldg(&crow[lane + 32]);
        float s = fmaf(a0.x, b0.x, fmaf(a0.y, b0.y, fmaf(a0.z, b0.z, a0.w * b0.w)))
                + fmaf(a1.x, b1.x, fmaf(a1.y, b1.y, fmaf(a1.z, b1.z, a1.w * b1.w)));
        #pragma unroll
        for (int off = 16; off > 0; off >>= 1)
            s += __shfl_down_sync(full, s, off);
        if (lane == 0) g_Wc[c * FDIM + k] = s;
    } else if (ww < CCLS * FDIM + CCLS) {
        int c = ww - CCLS * FDIM;
        const float4* brow = reinterpret_cast<const float4*>(b_sage);
        const float4* crow = reinterpret_cast<const float4*>(W_cls + c * FDIM);
        float4 a0 = __ldg(&brow[lane]);      float4 b0 = __ldg(&crow[lane]);
        float4 a1 = __ldg(&brow[lane + 32]); float4 b1 = __ldg(&crow[lane + 32]);
        float s = fmaf(a0.x, b0.x, fmaf(a0.y, b0.y, fmaf(a0.z, b0.z, a0.w * b0.w)))
                + fmaf(a1.x, b1.x, fmaf(a1.y, b1.y, fmaf(a1.z, b1.z, a1.w * b1.w)));
        #pragma unroll
        for (int off = 16; off > 0; off >>= 1)
            s += __shfl_down_sync(full, s, off);
        if (lane == 0) g_bc[c] = s + __ldg(&b_cls[c]);
    }
}

// ---------------------------------------------------------------------------
// Kernel 1: project. One warp per node: z[i] = x_all[n_id[i]] @ Wc, .w = 1.
// Also seeds acc[i] = z[i] (self loop + count).
// ---------------------------------------------------------------------------
__global__ void k_z(const float4* __restrict__ x_all4,
                    const int* __restrict__ n_id, int N) {
    __shared__ float sW[CCLS][FDIM];
    int t = threadIdx.x;
    for (int idx = t; idx < CCLS * FDIM; idx += blockDim.x)
        sW[idx >> 8][idx & 255] = g_Wc[idx];
    __syncthreads();

    int w    = (blockIdx.x * blockDim.x + t) >> 5;
    int lane = t & 31;
    if (w >= N) return;

    int row = __ldg(&n_id[w]);
    const float4* xp = x_all4 + (long long)row * F4;
    float4 a0 = __ldg(&xp[lane]);
    float4 a1 = __ldg(&xp[lane + 32]);

    int k0 = lane * 4, k1 = (lane + 32) * 4;
    float s0, s1, s2;
    {
        float t0, t1, t2;
        t0 = fmaf(a0.x, sW[0][k0], fmaf(a0.y, sW[0][k0+1], fmaf(a0.z, sW[0][k0+2], a0.w * sW[0][k0+3])));
        t1 = fmaf(a0.x, sW[1][k0], fmaf(a0.y, sW[1][k0+1], fmaf(a0.z, sW[1][k0+2], a0.w * sW[1][k0+3])));
        t2 = fmaf(a0.x, sW[2][k0], fmaf(a0.y, sW[2][k0+1], fmaf(a0.z, sW[2][k0+2], a0.w * sW[2][k0+3])));
        s0 = fmaf(a1.x, sW[0][k1], fmaf(a1.y, sW[0][k1+1], fmaf(a1.z, sW[0][k1+2], fmaf(a1.w, sW[0][k1+3], t0))));
        s1 = fmaf(a1.x, sW[1][k1], fmaf(a1.y, sW[1][k1+1], fmaf(a1.z, sW[1][k1+2], fmaf(a1.w, sW[1][k1+3], t1))));
        s2 = fmaf(a1.x, sW[2][k1], fmaf(a1.y, sW[2][k1+1], fmaf(a1.z, sW[2][k1+2], fmaf(a1.w, sW[2][k1+3], t2))));
    }
    const unsigned full = 0xffffffffu;
    #pragma unroll
    for (int off = 16; off > 0; off >>= 1) {
        s0 += __shfl_down_sync(full, s0, off);
        s1 += __shfl_down_sync(full, s1, off);
        s2 += __shfl_down_sync(full, s2, off);
    }
    if (lane == 0) {
        float4 zv = make_float4(s0, s1, s2, 1.0f);
        g_z[w]   = zv;   // projection
        g_acc[w] = zv;   // self-loop seed (count starts at 1)
    }
}

// ---------------------------------------------------------------------------
// Kernel 2: edge aggregation over 3-vectors. TWO edges per thread (int2
// loads, 2 independent z reads + 2 REDG in flight). z is 800KB, L2-resident.
// E is even for this dataset; guard handles odd tails anyway.
// ---------------------------------------------------------------------------
__global__ void k_edge(const int* __restrict__ src,
                       const int* __restrict__ dst, int E) {
    int p  = blockIdx.x * blockDim.x + threadIdx.x;   // pair index
    int e0 = p * 2;
    if (e0 >= E) return;
    if (e0 + 1 < E) {
        int2 s2v = __ldg(reinterpret_cast<const int2*>(src) + p);
        int2 d2v = __ldg(reinterpret_cast<const int2*>(dst) + p);
        float4 v0 = __ldg(&g_z[s2v.x]);
        float4 v1 = __ldg(&g_z[s2v.y]);
        asm volatile("red.global.add.v4.f32 [%0], {%1, %2, %3, %4};"
                     :: "l"(&g_acc[d2v.x]), "f"(v0.x), "f"(v0.y), "f"(v0.z), "f"(v0.w)
                     : "memory");
        asm volatile("red.global.add.v4.f32 [%0], {%1, %2, %3, %4};"
                     :: "l"(&g_acc[d2v.y]), "f"(v1.x), "f"(v1.y), "f"(v1.z), "f"(v1.w)
                     : "memory");
    } else {
        int s = __ldg(&src[e0]);
        int d = __ldg(&dst[e0]);
        float4 v = __ldg(&g_z[s]);
        asm volatile("red.global.add.v4.f32 [%0], {%1, %2, %3, %4};"
                     :: "l"(&g_acc[d]), "f"(v.x), "f"(v.y), "f"(v.z), "f"(v.w)
                     : "memory");
    }
}

// ---------------------------------------------------------------------------
// Kernel 3: finalize. mean, +bc, log_softmax with fast-math MUFU intrinsics
// (single-instruction __expf/__logf; error ~1e-6 rel, gate is 1e-3).
// ---------------------------------------------------------------------------
__global__ void k_final(float* __restrict__ out, int N) {
    int i = blockIdx.x * blockDim.x + threadIdx.x;
    if (i >= N) return;
    float4 a = g_acc[i];
    float inv = __frcp_rn(a.w);
    float s0 = fmaf(a.x, inv, g_bc[0]);
    float s1 = fmaf(a.y, inv, g_bc[1]);
    float s2 = fmaf(a.z, inv, g_bc[2]);
    float m   = fmaxf(s0, fmaxf(s1, s2));
    float e0 = __expf(s0 - m);
    float e1 = __expf(s1 - m);
    float e2 = __expf(s2 - m);
    float lse = m + __logf(e0 + e1 + e2);
    out[i * 3 + 0] = s0 - lse;
    out[i * 3 + 1] = s1 - lse;
    out[i * 3 + 2] = s2 - lse;
}

// ---------------------------------------------------------------------------
extern "C" void kernel_launch(void* const* d_in, const int* in_sizes, int n_in,
                              void* d_out, int out_size) {
    const float* x_all  = (const float*)d_in[0];
    const int*   n_id   = (const int*)  d_in[1];
    const int*   eidx   = (const int*)  d_in[2];
    const float* W_sage = (const float*)d_in[3];
    const float* b_sage = (const float*)d_in[4];
    const float* W_cls  = (const float*)d_in[5];
    const float* b_cls  = (const float*)d_in[6];
    float* out = (float*)d_out;

    int N = in_sizes[1];          // 50000
    int E = in_sizes[2] / 2;      // 300000
    const int* src = eidx;        // edge_index[0, :]
    const int* dst = eidx + E;    // edge_index[1, :]

    int init_threads = (CCLS * FDIM + CCLS) * 32;
    k_init<<<(init_threads + 255) / 256, 256>>>(W_sage, b_sage, W_cls, b_cls);

    long long zth = (long long)N * 32;
    k_z<<<(int)((zth + 255) / 256), 256>>>(
        reinterpret_cast<const float4*>(x_all), n_id, N);

    int pairs = (E + 1) / 2;
    k_edge<<<(pairs + 255) / 256, 256>>>(src, dst, E);

    k_final<<<(N + 255) / 256, 256>>>(out, N);
}